// round 14
// baseline (speedup 1.0000x reference)
#include <cuda_runtime.h>
#include <cuda_fp16.h>
#include <cstdint>

// Fixed problem shape
#define BB   8
#define CC   256
#define HH   64
#define WWD  64
#define OO   256
#define KKT  9
#define HWSZ 4096

#define TP   128         // pixel tile per CTA
#define NT   576         // 18 warps: 16 MMA consumers (4M x 4N) + 2 B-producers
#define NITER 18         // 2 c-chunks of 128 x 9 kpos (kpos innermost)

// ---- smem layout (bytes) ----
#define SM_T    0           // taps: 1152 x 16B = 18432
#define SM_A    18432       // 2 bufs x 65536 (256 o x 128 c fp16, two SW128 half-planes)
#define SM_B    149504      // 2 bufs x 32768 (128 px x 128 c fp16, two SW128 half-planes)
#define SMEM_TOTAL 215040

// Packed bilinear tap: 4 corner indices + 4 fp16 weights (mask-premultiplied)
struct __align__(16) Tap {
    unsigned short idx[4];
    __half2 w01;
    __half2 w23;
};

// ---- device scratch ----
__device__ __align__(16) __half g_wh[KKT * OO * CC];              // [k][o][c] fp16
__device__ __align__(16) __half g_xn[(size_t)BB * HWSZ * CC];     // NHWC fp16

// ---------------- merged prep kernel (ONE launch) ----------------
#define PREP_WBLK 2304
#define PREP_XBLK 8192
__global__ void prep_all(const float* __restrict__ w, const float* __restrict__ x) {
    __shared__ float tile[32][33];
    if (blockIdx.x < PREP_WBLK) {
        const int o = blockIdx.x & 255;
        const int k = blockIdx.x >> 8;
        const int c = threadIdx.x;
        float v = w[((size_t)o * CC + c) * KKT + k];
        g_wh[((size_t)k * OO + o) * CC + c] = __float2half_rn(v);
    } else {
        const int bidx = blockIdx.x - PREP_WBLK;
        const int bb  = bidx >> 10;
        const int rem = bidx & 1023;
        const int hw0 = (rem & 127) * 32;
        const int c0  = (rem >> 7) * 32;
        const int tx = threadIdx.x & 31;
        const int ty = threadIdx.x >> 5;
        const float* src = x + (size_t)bb * CC * HWSZ;
        #pragma unroll
        for (int i = 0; i < 32; i += 8)
            tile[ty + i][tx] = src[(size_t)(c0 + ty + i) * HWSZ + hw0 + tx];
        __syncthreads();
        __half* dst = g_xn + (size_t)bb * HWSZ * CC;
        #pragma unroll
        for (int i = 0; i < 32; i += 8)
            dst[(size_t)(hw0 + ty + i) * CC + c0 + tx] = __float2half_rn(tile[tx][ty + i]);
    }
}

// ---------------- helpers ----------------
__device__ __forceinline__ uint32_t s2u(const void* p) {
    uint32_t r;
    asm("{ .reg .u64 t; cvta.to.shared.u64 t, %1; cvt.u32.u64 %0, t; }" : "=r"(r) : "l"(p));
    return r;
}
__device__ __forceinline__ uint32_t sw128(uint32_t off) {
    return off ^ ((off >> 3) & 0x70);
}
__device__ __forceinline__ void bar_all() {
    asm volatile("bar.sync 1, %0;" :: "n"(NT) : "memory");
}
__device__ __forceinline__ void ldsm_x4(uint32_t addr, uint32_t& r0, uint32_t& r1,
                                        uint32_t& r2, uint32_t& r3) {
    asm volatile("ldmatrix.sync.aligned.m8n8.x4.shared.b16 {%0,%1,%2,%3}, [%4];"
                 : "=r"(r0), "=r"(r1), "=r"(r2), "=r"(r3) : "r"(addr));
}
__device__ __forceinline__ void mma_fp16(float* d, const uint32_t* a, uint32_t b0, uint32_t b1) {
    asm volatile("mma.sync.aligned.m16n8k16.row.col.f32.f16.f16.f32 "
                 "{%0,%1,%2,%3}, {%4,%5,%6,%7}, {%8,%9}, {%0,%1,%2,%3};"
                 : "+f"(d[0]), "+f"(d[1]), "+f"(d[2]), "+f"(d[3])
                 : "r"(a[0]), "r"(a[1]), "r"(a[2]), "r"(a[3]), "r"(b0), "r"(b1));
}
__device__ __forceinline__ void cp16(uint32_t dst, const void* src) {
    asm volatile("cp.async.cg.shared.global [%0], [%1], 16;" :: "r"(dst), "l"(src) : "memory");
}
__device__ __forceinline__ void cp_commit() { asm volatile("cp.async.commit_group;" ::: "memory"); }
__device__ __forceinline__ void cp_wait0()  { asm volatile("cp.async.wait_group 0;"  ::: "memory"); }

extern __shared__ char smraw[];

__global__ __launch_bounds__(NT, 1)
void dcn_ws_kernel(const float* __restrict__ offs,
                   const float* __restrict__ mask,
                   const float* __restrict__ bias,
                   float* __restrict__ out) {
    const int tid  = threadIdx.x;
    const int lane = tid & 31;
    const int wid  = tid >> 5;         // 0..17
    const int bb   = blockIdx.y;
    const int hw0  = blockIdx.x * TP;

    Tap* sT = (Tap*)(smraw + SM_T);
    const uint32_t uA = s2u(smraw + SM_A);
    const uint32_t uB = s2u(smraw + SM_B);

    // ---- taps: all 18 warps cooperate ----
    for (int i = tid; i < KKT * TP; i += NT) {
        const int k  = i / TP;
        const int p  = i - k * TP;
        const int hw = hw0 + p;
        const int h  = hw >> 6;
        const int w  = hw & 63;

        const float oy = offs[((size_t)bb * 18 + k * 2 + 0) * HWSZ + hw];
        const float ox = offs[((size_t)bb * 18 + k * 2 + 1) * HWSZ + hw];
        const float m  = mask[((size_t)bb * KKT + k) * HWSZ + hw];

        const float py = (float)(h - 1 + k / 3) + oy;
        const float px = (float)(w - 1 + k % 3) + ox;
        const float fy = floorf(py), fx = floorf(px);
        const int y0 = (int)fy, x0 = (int)fx;
        const float ly = py - fy, lx = px - fx;
        const float hy = 1.0f - ly, hx = 1.0f - lx;

        const bool vy0 = (y0 >= 0) && (y0 < HH);
        const bool vy1 = (y0 + 1 >= 0) && (y0 + 1 < HH);
        const bool vx0 = (x0 >= 0) && (x0 < WWD);
        const bool vx1 = (x0 + 1 >= 0) && (x0 + 1 < WWD);
        const int cy0 = min(max(y0, 0), HH - 1);
        const int cy1 = min(max(y0 + 1, 0), HH - 1);
        const int cx0 = min(max(x0, 0), WWD - 1);
        const int cx1 = min(max(x0 + 1, 0), WWD - 1);

        Tap t;
        t.idx[0] = (unsigned short)(cy0 * WWD + cx0);
        t.idx[1] = (unsigned short)(cy0 * WWD + cx1);
        t.idx[2] = (unsigned short)(cy1 * WWD + cx0);
        t.idx[3] = (unsigned short)(cy1 * WWD + cx1);
        const float w0v = (vy0 && vx0) ? hy * hx * m : 0.0f;
        const float w1v = (vy0 && vx1) ? hy * lx * m : 0.0f;
        const float w2v = (vy1 && vx0) ? ly * hx * m : 0.0f;
        const float w3v = (vy1 && vx1) ? ly * lx * m : 0.0f;
        t.w01 = __floats2half2_rn(w0v, w1v);
        t.w23 = __floats2half2_rn(w2v, w3v);
        sT[i] = t;
    }
    __syncthreads();

    const __half* __restrict__ xb = g_xn + (size_t)bb * HWSZ * CC;

    if (wid < 16) {
        // ================= CONSUMER: pure MMA stream =================
        const int warpM = wid >> 2;
        const int warpN = wid & 3;

        float acc[4][4][4];
        #pragma unroll
        for (int mf = 0; mf < 4; ++mf)
            #pragma unroll
            for (int nf = 0; nf < 4; ++nf)
                #pragma unroll
                for (int r = 0; r < 4; ++r) acc[mf][nf][r] = 0.0f;

        auto stageA = [&](int jt, int buf) {
            const int kpos = jt % KKT;
            const int c0   = (jt / KKT) * 128;
            const int q = tid & 7;
            const int r = tid >> 3;          // 0..63 (tid < 512)
            const uint32_t abase = uA + buf * 65536;
            const uint32_t swoff = sw128((uint32_t)(r * 128 + q * 16));
            #pragma unroll
            for (int rr = 0; rr < 4; ++rr) {
                const int row = r + rr * 64;
                const __half* src = g_wh + ((size_t)kpos * OO + row) * CC + c0 + q * 8;
                cp16(abase + swoff + rr * 64 * 128, src);
                cp16(abase + 32768 + swoff + rr * 64 * 128, src + 64);
            }
        };
        auto mmaKS = [&](int ks, int buf) {
            const int half = ks >> 2;
            const int ksl  = ks & 3;
            const uint32_t abase = uA + buf * 65536 + half * 32768;
            const uint32_t bbase = uB + buf * 32768 + half * 16384;
            uint32_t a[4][4];
            #pragma unroll
            for (int mf = 0; mf < 4; ++mf) {
                const uint32_t off = (uint32_t)((warpM * 64 + mf * 16 + (lane & 15)) * 128
                                                + ksl * 32 + (lane >> 4) * 16);
                ldsm_x4(abase + sw128(off), a[mf][0], a[mf][1], a[mf][2], a[mf][3]);
            }
            uint32_t bfr[4][2];
            #pragma unroll
            for (int pb = 0; pb < 2; ++pb) {
                const uint32_t off = (uint32_t)((warpN * 32 + pb * 16 + (lane & 15)) * 128
                                                + ksl * 32 + (lane >> 4) * 16);
                uint32_t r0, r1, r2, r3;
                ldsm_x4(bbase + sw128(off), r0, r1, r2, r3);
                bfr[pb * 2 + 0][0] = r0; bfr[pb * 2 + 0][1] = r2;
                bfr[pb * 2 + 1][0] = r1; bfr[pb * 2 + 1][1] = r3;
            }
            #pragma unroll
            for (int mf = 0; mf < 4; ++mf)
                #pragma unroll
                for (int nf = 0; nf < 4; ++nf)
                    mma_fp16(acc[mf][nf], a[mf], bfr[nf][0], bfr[nf][1]);
        };

        // prologue: stage A[0]
        stageA(0, 0);
        cp_commit();
        cp_wait0();
        bar_all();      // producers finished B[0]

        for (int it = 0; it < NITER; ++it) {
            const int buf  = it & 1;
            const bool more = (it + 1 < NITER);
            if (more) { stageA(it + 1, buf ^ 1); cp_commit(); }

            #pragma unroll
            for (int j = 0; j < 8; ++j) mmaKS(j, buf);

            if (more) cp_wait0();
            bar_all();
        }

        // epilogue: bias add + fp32 stores
        #pragma unroll
        for (int mf = 0; mf < 4; ++mf) {
            const int o0 = warpM * 64 + mf * 16 + (lane >> 2);
            const float bv0 = bias[o0];
            const float bv1 = bias[o0 + 8];
            #pragma unroll
            for (int nf = 0; nf < 4; ++nf) {
                const int p = hw0 + warpN * 32 + nf * 8 + (lane & 3) * 2;
                float* d0 = out + ((size_t)(bb * OO + o0)) * HWSZ + p;
                float* d1 = out + ((size_t)(bb * OO + o0 + 8)) * HWSZ + p;
                float2 v0, v1;
                v0.x = acc[mf][nf][0] + bv0; v0.y = acc[mf][nf][1] + bv0;
                v1.x = acc[mf][nf][2] + bv1; v1.y = acc[mf][nf][3] + bv1;
                *(float2*)d0 = v0;
                *(float2*)d1 = v1;
            }
        }
    } else {
        // ================= PRODUCER: B tile builder =================
        const int pw = wid - 16;           // 0..1 -> px [pw*64, pw*64+64)
        auto buildB = [&](int jt, int buf) {
            const int kpos = jt % KKT;
            const int c0   = (jt / KKT) * 128;
            const __half* xc = xb + c0 + 4 * lane;
            char* Bb = smraw + SM_B + buf * 32768 + (lane >> 4) * 16384;
            const Tap* tp = sT + kpos * TP + pw * 64;
            for (int b0 = 0; b0 < 64; b0 += 8) {
                uint2   gg[8][4];
                __half2 w01[8], w23[8];
                #pragma unroll
                for (int e = 0; e < 8; ++e) {
                    const Tap t = tp[b0 + e];
                    gg[e][0] = *(const uint2*)(xc + (size_t)t.idx[0] * CC);
                    gg[e][1] = *(const uint2*)(xc + (size_t)t.idx[1] * CC);
                    gg[e][2] = *(const uint2*)(xc + (size_t)t.idx[2] * CC);
                    gg[e][3] = *(const uint2*)(xc + (size_t)t.idx[3] * CC);
                    w01[e] = t.w01;
                    w23[e] = t.w23;
                }
                #pragma unroll
                for (int e = 0; e < 8; ++e) {
                    const int pp = pw * 64 + b0 + e;
                    const __half2 h0 = __low2half2(w01[e]);
                    const __half2 h1 = __high2half2(w01[e]);
                    const __half2 h2 = __low2half2(w23[e]);
                    const __half2 h3 = __high2half2(w23[e]);
                    __half2 vA = __hmul2(h0, *(__half2*)&gg[e][0].x);
                    vA = __hfma2(h1, *(__half2*)&gg[e][1].x, vA);
                    vA = __hfma2(h2, *(__half2*)&gg[e][2].x, vA);
                    vA = __hfma2(h3, *(__half2*)&gg[e][3].x, vA);
                    __half2 vB = __hmul2(h0, *(__half2*)&gg[e][0].y);
                    vB = __hfma2(h1, *(__half2*)&gg[e][1].y, vB);
                    vB = __hfma2(h2, *(__half2*)&gg[e][2].y, vB);
                    vB = __hfma2(h3, *(__half2*)&gg[e][3].y, vB);
                    uint2 pk;
                    pk.x = *(uint32_t*)&vA;
                    pk.y = *(uint32_t*)&vB;
                    *(uint2*)(Bb + sw128((uint32_t)(pp * 128 + (lane & 15) * 8))) = pk;
                }
            }
        };

        // prologue: build B[0]
        buildB(0, 0);
        bar_all();

        for (int it = 0; it < NITER; ++it) {
            const bool more = (it + 1 < NITER);
            if (more) buildB(it + 1, (it & 1) ^ 1);
            bar_all();
        }
        // producers exit (no epilogue work)
    }
}

extern "C" void kernel_launch(void* const* d_in, const int* in_sizes, int n_in,
                              void* d_out, int out_size) {
    const float* inp    = (const float*)d_in[0];  // [8,256,64,64]
    const float* offs   = (const float*)d_in[1];  // [8,18,64,64]
    const float* mask   = (const float*)d_in[2];  // [8,9,64,64]
    const float* weight = (const float*)d_in[3];  // [256,256,3,3]
    const float* bias   = (const float*)d_in[4];  // [256]
    float* out = (float*)d_out;                   // [8,256,64,64]

    cudaFuncSetAttribute(dcn_ws_kernel,
                         cudaFuncAttributeMaxDynamicSharedMemorySize, SMEM_TOTAL);

    prep_all<<<PREP_WBLK + PREP_XBLK, 256>>>(weight, inp);

    dim3 grid(HWSZ / TP, BB);   // (32, 8) = 256 CTAs
    dcn_ws_kernel<<<grid, NT, SMEM_TOTAL>>>(offs, mask, bias, out);
}

// round 15
// speedup vs baseline: 1.2381x; 1.2381x over previous
#include <cuda_runtime.h>
#include <cuda_fp16.h>
#include <cstdint>

// Fixed problem shape
#define BB   8
#define CC   256
#define HH   64
#define WWD  64
#define OO   256
#define KKT  9
#define HWSZ 4096

#define TP   64          // pixel tile per CTA (256 o x 64 px), 2 CTAs/SM
#define NT   256         // 8 warps: 4 M-groups x 2 N-groups
#define NITER 18         // 2 c-chunks of 128 x 9 kpos (kpos innermost)

// ---- smem layout (bytes), per CTA = 107520 -> 2 CTAs = 215040 < 227KB ----
#define SM_T    0           // taps: 576 x 16B = 9216
#define SM_A    9216        // 1 buf x 65536 (256 o x 128 c fp16, two SW128 half-planes)
#define SM_B    74752       // 2 bufs x 16384 (64 px x 128 c fp16, two half-planes)
#define SMEM_TOTAL 107520

// Packed bilinear tap: 4 corner indices + 4 fp16 weights (mask-premultiplied)
struct __align__(16) Tap {
    unsigned short idx[4];
    __half2 w01;
    __half2 w23;
};

// ---- device scratch ----
__device__ __align__(16) __half g_wh[KKT * OO * CC];              // [k][o][c] fp16
__device__ __align__(16) __half g_xn[(size_t)BB * HWSZ * CC];     // NHWC fp16

// ---------------- merged prep kernel (ONE launch) ----------------
#define PREP_WBLK 2304
#define PREP_XBLK 8192
__global__ void prep_all(const float* __restrict__ w, const float* __restrict__ x) {
    __shared__ float tile[32][33];
    if (blockIdx.x < PREP_WBLK) {
        const int o = blockIdx.x & 255;
        const int k = blockIdx.x >> 8;
        const int c = threadIdx.x;
        float v = w[((size_t)o * CC + c) * KKT + k];
        g_wh[((size_t)k * OO + o) * CC + c] = __float2half_rn(v);
    } else {
        const int bidx = blockIdx.x - PREP_WBLK;
        const int bb  = bidx >> 10;
        const int rem = bidx & 1023;
        const int hw0 = (rem & 127) * 32;
        const int c0  = (rem >> 7) * 32;
        const int tx = threadIdx.x & 31;
        const int ty = threadIdx.x >> 5;
        const float* src = x + (size_t)bb * CC * HWSZ;
        #pragma unroll
        for (int i = 0; i < 32; i += 8)
            tile[ty + i][tx] = src[(size_t)(c0 + ty + i) * HWSZ + hw0 + tx];
        __syncthreads();
        __half* dst = g_xn + (size_t)bb * HWSZ * CC;
        #pragma unroll
        for (int i = 0; i < 32; i += 8)
            dst[(size_t)(hw0 + ty + i) * CC + c0 + tx] = __float2half_rn(tile[tx][ty + i]);
    }
}

// ---------------- helpers ----------------
__device__ __forceinline__ uint32_t s2u(const void* p) {
    uint32_t r;
    asm("{ .reg .u64 t; cvta.to.shared.u64 t, %1; cvt.u32.u64 %0, t; }" : "=r"(r) : "l"(p));
    return r;
}
__device__ __forceinline__ uint32_t sw128(uint32_t off) {
    return off ^ ((off >> 3) & 0x70);
}
__device__ __forceinline__ void ldsm_x4(uint32_t addr, uint32_t& r0, uint32_t& r1,
                                        uint32_t& r2, uint32_t& r3) {
    asm volatile("ldmatrix.sync.aligned.m8n8.x4.shared.b16 {%0,%1,%2,%3}, [%4];"
                 : "=r"(r0), "=r"(r1), "=r"(r2), "=r"(r3) : "r"(addr));
}
__device__ __forceinline__ void mma_fp16(float* d, const uint32_t* a, uint32_t b0, uint32_t b1) {
    asm volatile("mma.sync.aligned.m16n8k16.row.col.f32.f16.f16.f32 "
                 "{%0,%1,%2,%3}, {%4,%5,%6,%7}, {%8,%9}, {%0,%1,%2,%3};"
                 : "+f"(d[0]), "+f"(d[1]), "+f"(d[2]), "+f"(d[3])
                 : "r"(a[0]), "r"(a[1]), "r"(a[2]), "r"(a[3]), "r"(b0), "r"(b1));
}
__device__ __forceinline__ void cp16(uint32_t dst, const void* src) {
    asm volatile("cp.async.cg.shared.global [%0], [%1], 16;" :: "r"(dst), "l"(src) : "memory");
}
__device__ __forceinline__ void cp_commit() { asm volatile("cp.async.commit_group;" ::: "memory"); }
__device__ __forceinline__ void cp_wait0()  { asm volatile("cp.async.wait_group 0;"  ::: "memory"); }

extern __shared__ char smraw[];

__global__ __launch_bounds__(NT, 2)
void dcn_occ2_kernel(const float* __restrict__ offs,
                     const float* __restrict__ mask,
                     const float* __restrict__ bias,
                     float* __restrict__ out) {
    const int tid  = threadIdx.x;
    const int lane = tid & 31;
    const int wid  = tid >> 5;         // 0..7
    const int warpM = wid >> 1;        // 0..3 -> 64 o-rows
    const int warpN = wid & 1;         // 0..1 -> 32 px
    const int bb   = blockIdx.y;
    const int hw0  = blockIdx.x * TP;

    Tap* sT = (Tap*)(smraw + SM_T);
    const uint32_t uA = s2u(smraw + SM_A);
    const uint32_t uB = s2u(smraw + SM_B);

    // ---- taps: bilinear corner indices + mask-premultiplied fp16 weights ----
    for (int i = tid; i < KKT * TP; i += NT) {
        const int k  = i / TP;
        const int p  = i - k * TP;
        const int hw = hw0 + p;
        const int h  = hw >> 6;
        const int w  = hw & 63;

        const float oy = offs[((size_t)bb * 18 + k * 2 + 0) * HWSZ + hw];
        const float ox = offs[((size_t)bb * 18 + k * 2 + 1) * HWSZ + hw];
        const float m  = mask[((size_t)bb * KKT + k) * HWSZ + hw];

        const float py = (float)(h - 1 + k / 3) + oy;
        const float px = (float)(w - 1 + k % 3) + ox;
        const float fy = floorf(py), fx = floorf(px);
        const int y0 = (int)fy, x0 = (int)fx;
        const float ly = py - fy, lx = px - fx;
        const float hy = 1.0f - ly, hx = 1.0f - lx;

        const bool vy0 = (y0 >= 0) && (y0 < HH);
        const bool vy1 = (y0 + 1 >= 0) && (y0 + 1 < HH);
        const bool vx0 = (x0 >= 0) && (x0 < WWD);
        const bool vx1 = (x0 + 1 >= 0) && (x0 + 1 < WWD);
        const int cy0 = min(max(y0, 0), HH - 1);
        const int cy1 = min(max(y0 + 1, 0), HH - 1);
        const int cx0 = min(max(x0, 0), WWD - 1);
        const int cx1 = min(max(x0 + 1, 0), WWD - 1);

        Tap t;
        t.idx[0] = (unsigned short)(cy0 * WWD + cx0);
        t.idx[1] = (unsigned short)(cy0 * WWD + cx1);
        t.idx[2] = (unsigned short)(cy1 * WWD + cx0);
        t.idx[3] = (unsigned short)(cy1 * WWD + cx1);
        const float w0v = (vy0 && vx0) ? hy * hx * m : 0.0f;
        const float w1v = (vy0 && vx1) ? hy * lx * m : 0.0f;
        const float w2v = (vy1 && vx0) ? ly * hx * m : 0.0f;
        const float w3v = (vy1 && vx1) ? ly * lx * m : 0.0f;
        t.w01 = __floats2half2_rn(w0v, w1v);
        t.w23 = __floats2half2_rn(w2v, w3v);
        sT[i] = t;
    }

    const __half* __restrict__ xb = g_xn + (size_t)bb * HWSZ * CC;

    float acc[4][4][4];
    #pragma unroll
    for (int mf = 0; mf < 4; ++mf)
        #pragma unroll
        for (int nf = 0; nf < 4; ++nf)
            #pragma unroll
            for (int r = 0; r < 4; ++r) acc[mf][nf][r] = 0.0f;

    // ---- stage A: 256 o x 128 c fp16 as two SW128 half-planes (SINGLE buffer) ----
    auto stageA = [&](int jt) {
        const int kpos = jt % KKT;
        const int c0   = (jt / KKT) * 128;
        const int q = tid & 7;          // 16B chunk within 128B row
        const int r = tid >> 3;         // 0..31
        const uint32_t swoff = sw128((uint32_t)(r * 128 + q * 16));
        #pragma unroll
        for (int rr = 0; rr < 8; ++rr) {
            const int row = r + rr * 32;
            const __half* src = g_wh + ((size_t)kpos * OO + row) * CC + c0 + q * 8;
            const uint32_t so = swoff + rr * 32 * 128;
            cp16(uA + so, src);              // half-plane 0 (c 0..63)
            cp16(uA + 32768 + so, src + 64); // half-plane 1 (c 64..127)
        }
    };

    // Per-pixel gather pipeline: 2 slots x (4 corners uint2 + packed weights)
    uint2   g[2][4];
    __half2 wA[2], wB[2];
    auto loadP = [&](int jt, int p, int s) {
        const int kpos = jt % KKT;
        const int c0   = (jt / KKT) * 128;
        const __half* xc = xb + c0 + 4 * lane;
        const Tap t = sT[kpos * TP + wid * 8 + p];   // single LDS.128
        g[s][0] = *(const uint2*)(xc + (size_t)t.idx[0] * CC);
        g[s][1] = *(const uint2*)(xc + (size_t)t.idx[1] * CC);
        g[s][2] = *(const uint2*)(xc + (size_t)t.idx[2] * CC);
        g[s][3] = *(const uint2*)(xc + (size_t)t.idx[3] * CC);
        wA[s] = t.w01;
        wB[s] = t.w23;
    };
    auto storeP = [&](int p, int s, int buf) {
        char* Bb = smraw + SM_B + buf * 16384 + (lane >> 4) * 8192;
        const int pp = wid * 8 + p;                   // 0..63
        const __half2 h0 = __low2half2(wA[s]);
        const __half2 h1 = __high2half2(wA[s]);
        const __half2 h2 = __low2half2(wB[s]);
        const __half2 h3 = __high2half2(wB[s]);
        __half2 vA = __hmul2(h0, *(__half2*)&g[s][0].x);
        vA = __hfma2(h1, *(__half2*)&g[s][1].x, vA);
        vA = __hfma2(h2, *(__half2*)&g[s][2].x, vA);
        vA = __hfma2(h3, *(__half2*)&g[s][3].x, vA);
        __half2 vBv = __hmul2(h0, *(__half2*)&g[s][0].y);
        vBv = __hfma2(h1, *(__half2*)&g[s][1].y, vBv);
        vBv = __hfma2(h2, *(__half2*)&g[s][2].y, vBv);
        vBv = __hfma2(h3, *(__half2*)&g[s][3].y, vBv);
        uint2 pk;
        pk.x = *(uint32_t*)&vA;
        pk.y = *(uint32_t*)&vBv;
        *(uint2*)(Bb + sw128((uint32_t)(pp * 128 + (lane & 15) * 8))) = pk;
    };
    auto mmaKS = [&](int ks, int buf) {
        const int half = ks >> 2;
        const int ksl  = ks & 3;
        const uint32_t abase = uA + half * 32768;
        const uint32_t bbase = uB + buf * 16384 + half * 8192;
        uint32_t a[4][4];
        #pragma unroll
        for (int mf = 0; mf < 4; ++mf) {
            const uint32_t off = (uint32_t)((warpM * 64 + mf * 16 + (lane & 15)) * 128
                                            + ksl * 32 + (lane >> 4) * 16);
            ldsm_x4(abase + sw128(off), a[mf][0], a[mf][1], a[mf][2], a[mf][3]);
        }
        uint32_t bfr[4][2];
        #pragma unroll
        for (int pb = 0; pb < 2; ++pb) {
            const uint32_t off = (uint32_t)((warpN * 32 + pb * 16 + (lane & 15)) * 128
                                            + ksl * 32 + (lane >> 4) * 16);
            uint32_t r0, r1, r2, r3;
            ldsm_x4(bbase + sw128(off), r0, r1, r2, r3);
            bfr[pb * 2 + 0][0] = r0; bfr[pb * 2 + 0][1] = r2;
            bfr[pb * 2 + 1][0] = r1; bfr[pb * 2 + 1][1] = r3;
        }
        #pragma unroll
        for (int mf = 0; mf < 4; ++mf)
            #pragma unroll
            for (int nf = 0; nf < 4; ++nf)
                mma_fp16(acc[mf][nf], a[mf], bfr[nf][0], bfr[nf][1]);
    };

    // ---- prologue: A[0] staged, B[0] built ----
    stageA(0);
    cp_commit();
    __syncthreads();          // taps ready (B build reads taps)
    #pragma unroll
    for (int p = 0; p < 8; ++p) { loadP(0, p, p & 1); storeP(p, p & 1, 0); }
    cp_wait0();
    __syncthreads();          // A[0] + B[0] visible

    // ---- main loop: mma(it) + B-build(it+1), then restage A in the barrier gap ----
    for (int it = 0; it < NITER; ++it) {
        const int buf  = it & 1;
        const int nbuf = buf ^ 1;
        const bool more = (it + 1 < NITER);
        if (more) { loadP(it + 1, 0, 0); loadP(it + 1, 1, 1); }

        #pragma unroll
        for (int j = 0; j < 8; ++j) {
            mmaKS(j, buf);
            if (more) {
                storeP(j, j & 1, nbuf);
                if (j < 6) loadP(it + 1, j + 2, j & 1);
            }
        }

        if (more) {
            __syncthreads();      // all warps done reading A[it] (and B[nbuf] written)
            stageA(it + 1);       // overwrite the single A buffer
            cp_commit();
            cp_wait0();
            __syncthreads();      // A[it+1] visible
        }
    }

    // ---- epilogue: bias add + fp32 stores ----
    #pragma unroll
    for (int mf = 0; mf < 4; ++mf) {
        const int o0 = warpM * 64 + mf * 16 + (lane >> 2);
        const float bv0 = bias[o0];
        const float bv1 = bias[o0 + 8];
        #pragma unroll
        for (int nf = 0; nf < 4; ++nf) {
            const int p = hw0 + warpN * 32 + nf * 8 + (lane & 3) * 2;
            float* d0 = out + ((size_t)(bb * OO + o0)) * HWSZ + p;
            float* d1 = out + ((size_t)(bb * OO + o0 + 8)) * HWSZ + p;
            float2 v0, v1;
            v0.x = acc[mf][nf][0] + bv0; v0.y = acc[mf][nf][1] + bv0;
            v1.x = acc[mf][nf][2] + bv1; v1.y = acc[mf][nf][3] + bv1;
            *(float2*)d0 = v0;
            *(float2*)d1 = v1;
        }
    }
}

extern "C" void kernel_launch(void* const* d_in, const int* in_sizes, int n_in,
                              void* d_out, int out_size) {
    const float* inp    = (const float*)d_in[0];  // [8,256,64,64]
    const float* offs   = (const float*)d_in[1];  // [8,18,64,64]
    const float* mask   = (const float*)d_in[2];  // [8,9,64,64]
    const float* weight = (const float*)d_in[3];  // [256,256,3,3]
    const float* bias   = (const float*)d_in[4];  // [256]
    float* out = (float*)d_out;                   // [8,256,64,64]

    cudaFuncSetAttribute(dcn_occ2_kernel,
                         cudaFuncAttributeMaxDynamicSharedMemorySize, SMEM_TOTAL);

    prep_all<<<PREP_WBLK + PREP_XBLK, 256>>>(weight, inp);

    dim3 grid(HWSZ / TP, BB);   // (64, 8) = 512 CTAs, 2 per SM
    dcn_occ2_kernel<<<grid, NT, SMEM_TOTAL>>>(offs, mask, bias, out);
}

// round 16
// speedup vs baseline: 1.3668x; 1.1040x over previous
#include <cuda_runtime.h>
#include <cuda_fp16.h>
#include <cstdint>

// Fixed problem shape
#define BB   8
#define CC   256
#define HH   64
#define WWD  64
#define OO   256
#define KKT  9
#define HWSZ 4096

#define TP   128         // pixel tile per GEMM CTA
#define NT   512         // 16 warps: 4 M-warps x 4 N-warps
#define NITER 18         // 2 c-chunks of 128 x 9 kpos

// ---- GEMM smem layout (bytes): A 2x64KB + B 2x32KB = 192KB ----
#define SM_A    0
#define SM_B    131072
#define SMEM_TOTAL 196608

// Packed bilinear tap
struct __align__(16) Tap {
    unsigned short idx[4];
    __half2 w01;
    __half2 w23;
};

// ---- device scratch ----
__device__ __align__(16) __half g_wh[KKT * OO * CC];                       // [k][o][c] fp16
__device__ __align__(16) __half g_xn[(size_t)BB * HWSZ * CC];              // NHWC fp16
__device__ __align__(16) __half g_cols[(size_t)BB * KKT * HWSZ * CC];      // im2col, 151MB

// ---------------- merged prep kernel ----------------
#define PREP_WBLK 2304
#define PREP_XBLK 8192
__global__ void prep_all(const float* __restrict__ w, const float* __restrict__ x) {
    __shared__ float tile[32][33];
    if (blockIdx.x < PREP_WBLK) {
        const int o = blockIdx.x & 255;
        const int k = blockIdx.x >> 8;
        const int c = threadIdx.x;
        float v = w[((size_t)o * CC + c) * KKT + k];
        g_wh[((size_t)k * OO + o) * CC + c] = __float2half_rn(v);
    } else {
        const int bidx = blockIdx.x - PREP_WBLK;
        const int bb  = bidx >> 10;
        const int rem = bidx & 1023;
        const int hw0 = (rem & 127) * 32;
        const int c0  = (rem >> 7) * 32;
        const int tx = threadIdx.x & 31;
        const int ty = threadIdx.x >> 5;
        const float* src = x + (size_t)bb * CC * HWSZ;
        #pragma unroll
        for (int i = 0; i < 32; i += 8)
            tile[ty + i][tx] = src[(size_t)(c0 + ty + i) * HWSZ + hw0 + tx];
        __syncthreads();
        __half* dst = g_xn + (size_t)bb * HWSZ * CC;
        #pragma unroll
        for (int i = 0; i < 32; i += 8)
            dst[(size_t)(hw0 + ty + i) * CC + c0 + tx] = __float2half_rn(tile[tx][ty + i]);
    }
}

// ---------------- im2col kernel: gathers + interp -> g_cols ----------------
#define IC_PX 64
__global__ __launch_bounds__(256)
void im2col_kernel(const float* __restrict__ offs, const float* __restrict__ mask) {
    __shared__ Tap taps[IC_PX];
    const int tid  = threadIdx.x;
    const int hw0  = blockIdx.x * IC_PX;
    const int kpos = blockIdx.y;
    const int bb   = blockIdx.z;

    if (tid < IC_PX) {
        const int hw = hw0 + tid;
        const int h  = hw >> 6;
        const int w  = hw & 63;
        const float oy = offs[((size_t)bb * 18 + kpos * 2 + 0) * HWSZ + hw];
        const float ox = offs[((size_t)bb * 18 + kpos * 2 + 1) * HWSZ + hw];
        const float m  = mask[((size_t)bb * KKT + kpos) * HWSZ + hw];

        const float py = (float)(h - 1 + kpos / 3) + oy;
        const float px = (float)(w - 1 + kpos % 3) + ox;
        const float fy = floorf(py), fx = floorf(px);
        const int y0 = (int)fy, x0 = (int)fx;
        const float ly = py - fy, lx = px - fx;
        const float hy = 1.0f - ly, hx = 1.0f - lx;

        const bool vy0 = (y0 >= 0) && (y0 < HH);
        const bool vy1 = (y0 + 1 >= 0) && (y0 + 1 < HH);
        const bool vx0 = (x0 >= 0) && (x0 < WWD);
        const bool vx1 = (x0 + 1 >= 0) && (x0 + 1 < WWD);
        const int cy0 = min(max(y0, 0), HH - 1);
        const int cy1 = min(max(y0 + 1, 0), HH - 1);
        const int cx0 = min(max(x0, 0), WWD - 1);
        const int cx1 = min(max(x0 + 1, 0), WWD - 1);

        Tap t;
        t.idx[0] = (unsigned short)(cy0 * WWD + cx0);
        t.idx[1] = (unsigned short)(cy0 * WWD + cx1);
        t.idx[2] = (unsigned short)(cy1 * WWD + cx0);
        t.idx[3] = (unsigned short)(cy1 * WWD + cx1);
        const float w0v = (vy0 && vx0) ? hy * hx * m : 0.0f;
        const float w1v = (vy0 && vx1) ? hy * lx * m : 0.0f;
        const float w2v = (vy1 && vx0) ? ly * hx * m : 0.0f;
        const float w3v = (vy1 && vx1) ? ly * lx * m : 0.0f;
        t.w01 = __floats2half2_rn(w0v, w1v);
        t.w23 = __floats2half2_rn(w2v, w3v);
        taps[tid] = t;
    }
    __syncthreads();

    const int wid  = tid >> 5;
    const int lane = tid & 31;
    const __half* __restrict__ xb = g_xn + (size_t)bb * HWSZ * CC + lane * 8;
    __half* __restrict__ outp = g_cols
        + ((size_t)(bb * KKT + kpos) * HWSZ + hw0) * CC;

    #pragma unroll
    for (int e = 0; e < 8; ++e) {
        const int p = wid * 8 + e;
        const Tap t = taps[p];
        uint4 c0 = *(const uint4*)(xb + (size_t)t.idx[0] * CC);
        uint4 c1 = *(const uint4*)(xb + (size_t)t.idx[1] * CC);
        uint4 c2 = *(const uint4*)(xb + (size_t)t.idx[2] * CC);
        uint4 c3 = *(const uint4*)(xb + (size_t)t.idx[3] * CC);
        const __half2 h0 = __low2half2(t.w01);
        const __half2 h1 = __high2half2(t.w01);
        const __half2 h2 = __low2half2(t.w23);
        const __half2 h3 = __high2half2(t.w23);
        const __half2* p0 = (const __half2*)&c0;
        const __half2* p1 = (const __half2*)&c1;
        const __half2* p2 = (const __half2*)&c2;
        const __half2* p3 = (const __half2*)&c3;
        uint4 v;
        __half2* pv = (__half2*)&v;
        #pragma unroll
        for (int j = 0; j < 4; ++j) {
            __half2 r = __hmul2(h0, p0[j]);
            r = __hfma2(h1, p1[j], r);
            r = __hfma2(h2, p2[j], r);
            r = __hfma2(h3, p3[j], r);
            pv[j] = r;
        }
        *(uint4*)(outp + (size_t)p * CC + lane * 8) = v;
    }
}

// ---------------- helpers ----------------
__device__ __forceinline__ uint32_t s2u(const void* p) {
    uint32_t r;
    asm("{ .reg .u64 t; cvta.to.shared.u64 t, %1; cvt.u32.u64 %0, t; }" : "=r"(r) : "l"(p));
    return r;
}
__device__ __forceinline__ uint32_t sw128(uint32_t off) {
    return off ^ ((off >> 3) & 0x70);
}
__device__ __forceinline__ void ldsm_x4(uint32_t addr, uint32_t& r0, uint32_t& r1,
                                        uint32_t& r2, uint32_t& r3) {
    asm volatile("ldmatrix.sync.aligned.m8n8.x4.shared.b16 {%0,%1,%2,%3}, [%4];"
                 : "=r"(r0), "=r"(r1), "=r"(r2), "=r"(r3) : "r"(addr));
}
__device__ __forceinline__ void mma_fp16(float* d, const uint32_t* a, uint32_t b0, uint32_t b1) {
    asm volatile("mma.sync.aligned.m16n8k16.row.col.f32.f16.f16.f32 "
                 "{%0,%1,%2,%3}, {%4,%5,%6,%7}, {%8,%9}, {%0,%1,%2,%3};"
                 : "+f"(d[0]), "+f"(d[1]), "+f"(d[2]), "+f"(d[3])
                 : "r"(a[0]), "r"(a[1]), "r"(a[2]), "r"(a[3]), "r"(b0), "r"(b1));
}
__device__ __forceinline__ void cp16(uint32_t dst, const void* src) {
    asm volatile("cp.async.cg.shared.global [%0], [%1], 16;" :: "r"(dst), "l"(src) : "memory");
}
__device__ __forceinline__ void cp_commit() { asm volatile("cp.async.commit_group;" ::: "memory"); }
__device__ __forceinline__ void cp_wait0()  { asm volatile("cp.async.wait_group 0;"  ::: "memory"); }

extern __shared__ char smraw[];

// ---------------- GEMM kernel: out = W x cols (all operands staged via cp.async) ----------------
__global__ __launch_bounds__(NT, 1)
void dcn_gemm_kernel(const float* __restrict__ bias, float* __restrict__ out) {
    const int tid  = threadIdx.x;
    const int lane = tid & 31;
    const int wid  = tid >> 5;
    const int warpM = wid >> 2;
    const int warpN = wid & 3;
    const int bb   = blockIdx.y;
    const int hw0  = blockIdx.x * TP;

    const uint32_t uA = s2u(smraw + SM_A);
    const uint32_t uB = s2u(smraw + SM_B);

    float acc[4][4][4];
    #pragma unroll
    for (int mf = 0; mf < 4; ++mf)
        #pragma unroll
        for (int nf = 0; nf < 4; ++nf)
            #pragma unroll
            for (int r = 0; r < 4; ++r) acc[mf][nf][r] = 0.0f;

    // stage A: 256 o x 128 c fp16, two SW128 half-planes
    auto stageA = [&](int jt, int buf) {
        const int kpos = jt % KKT;
        const int c0   = (jt / KKT) * 128;
        const int q = tid & 7;
        const int r = tid >> 3;          // 0..63
        const uint32_t abase = uA + buf * 65536;
        const uint32_t swoff = sw128((uint32_t)(r * 128 + q * 16));
        #pragma unroll
        for (int rr = 0; rr < 4; ++rr) {
            const int row = r + rr * 64;
            const __half* src = g_wh + ((size_t)kpos * OO + row) * CC + c0 + q * 8;
            cp16(abase + swoff + rr * 64 * 128, src);
            cp16(abase + 32768 + swoff + rr * 64 * 128, src + 64);
        }
    };
    // stage B: 128 px x 128 c from g_cols (contiguous reads), two half-planes
    auto stageB = [&](int jt, int buf) {
        const int kpos = jt % KKT;
        const int c0   = (jt / KKT) * 128;
        const __half* colb = g_cols
            + ((size_t)(bb * KKT + kpos) * HWSZ + hw0) * CC + c0;
        const uint32_t bbase = uB + buf * 32768;
        #pragma unroll
        for (int rr = 0; rr < 4; ++rr) {
            const int m = tid + rr * NT;          // 0..2047
            const int half = m >> 10;
            const int pp   = (m >> 3) & 127;
            const int q    = m & 7;
            const __half* src = colb + (size_t)pp * CC + half * 64 + q * 8;
            cp16(bbase + half * 16384 + sw128((uint32_t)(pp * 128 + q * 16)), src);
        }
    };
    auto mmaKS = [&](int ks, int buf) {
        const int half = ks >> 2;
        const int ksl  = ks & 3;
        const uint32_t abase = uA + buf * 65536 + half * 32768;
        const uint32_t bbase = uB + buf * 32768 + half * 16384;
        uint32_t a[4][4];
        #pragma unroll
        for (int mf = 0; mf < 4; ++mf) {
            const uint32_t off = (uint32_t)((warpM * 64 + mf * 16 + (lane & 15)) * 128
                                            + ksl * 32 + (lane >> 4) * 16);
            ldsm_x4(abase + sw128(off), a[mf][0], a[mf][1], a[mf][2], a[mf][3]);
        }
        uint32_t bfr[4][2];
        #pragma unroll
        for (int pb = 0; pb < 2; ++pb) {
            const uint32_t off = (uint32_t)((warpN * 32 + pb * 16 + (lane & 15)) * 128
                                            + ksl * 32 + (lane >> 4) * 16);
            uint32_t r0, r1, r2, r3;
            ldsm_x4(bbase + sw128(off), r0, r1, r2, r3);
            bfr[pb * 2 + 0][0] = r0; bfr[pb * 2 + 0][1] = r2;
            bfr[pb * 2 + 1][0] = r1; bfr[pb * 2 + 1][1] = r3;
        }
        #pragma unroll
        for (int mf = 0; mf < 4; ++mf)
            #pragma unroll
            for (int nf = 0; nf < 4; ++nf)
                mma_fp16(acc[mf][nf], a[mf], bfr[nf][0], bfr[nf][1]);
    };

    // prologue
    stageA(0, 0);
    stageB(0, 0);
    cp_commit();
    cp_wait0();
    __syncthreads();

    for (int it = 0; it < NITER; ++it) {
        const int buf  = it & 1;
        const bool more = (it + 1 < NITER);
        if (more) { stageA(it + 1, buf ^ 1); stageB(it + 1, buf ^ 1); cp_commit(); }

        #pragma unroll
        for (int j = 0; j < 8; ++j) mmaKS(j, buf);

        if (more) cp_wait0();
        __syncthreads();
    }

    // epilogue: bias add + fp32 stores
    #pragma unroll
    for (int mf = 0; mf < 4; ++mf) {
        const int o0 = warpM * 64 + mf * 16 + (lane >> 2);
        const float bv0 = bias[o0];
        const float bv1 = bias[o0 + 8];
        #pragma unroll
        for (int nf = 0; nf < 4; ++nf) {
            const int p = hw0 + warpN * 32 + nf * 8 + (lane & 3) * 2;
            float* d0 = out + ((size_t)(bb * OO + o0)) * HWSZ + p;
            float* d1 = out + ((size_t)(bb * OO + o0 + 8)) * HWSZ + p;
            float2 v0, v1;
            v0.x = acc[mf][nf][0] + bv0; v0.y = acc[mf][nf][1] + bv0;
            v1.x = acc[mf][nf][2] + bv1; v1.y = acc[mf][nf][3] + bv1;
            *(float2*)d0 = v0;
            *(float2*)d1 = v1;
        }
    }
}

extern "C" void kernel_launch(void* const* d_in, const int* in_sizes, int n_in,
                              void* d_out, int out_size) {
    const float* inp    = (const float*)d_in[0];  // [8,256,64,64]
    const float* offs   = (const float*)d_in[1];  // [8,18,64,64]
    const float* mask   = (const float*)d_in[2];  // [8,9,64,64]
    const float* weight = (const float*)d_in[3];  // [256,256,3,3]
    const float* bias   = (const float*)d_in[4];  // [256]
    float* out = (float*)d_out;                   // [8,256,64,64]

    cudaFuncSetAttribute(dcn_gemm_kernel,
                         cudaFuncAttributeMaxDynamicSharedMemorySize, SMEM_TOTAL);

    prep_all<<<PREP_WBLK + PREP_XBLK, 256>>>(weight, inp);
    im2col_kernel<<<dim3(HWSZ / IC_PX, KKT, BB), 256>>>(offs, mask);

    dim3 grid(HWSZ / TP, BB);   // (32, 8) = 256 CTAs
    dcn_gemm_kernel<<<grid, NT, SMEM_TOTAL>>>(bias, out);
}